// round 9
// baseline (speedup 1.0000x reference)
#include <cuda_runtime.h>

// KeopsDFTD3Module: all-pairs D3-BJ dispersion energy, N=8192, scalar output.
//   D_ij = -s6/(d2^3 + T6) - s8/(d2^4 + T8),  T6=(a1+a2)^6+eps, T8=(a1+a2)^8+eps
//   diagonal masked out. Output = sum_ij D_ij.
//
// R7: exact-symmetry triangle (d2 = ni+nj-2ri.rj is bitwise symmetric) with
// TWO packed f32x2 i-streams per thread for ILP (the R6 single-stream version
// was dependency-chain bound: fma% fell 57->39). 16 tiles of 512 atoms,
// 136 unordered tile pairs x 8 j-chunks = 1088 identical CTAs. Off-diagonal
// pairs weighted 2; self-pairs removed analytically. Fused last-block reduce.
//
// Inputs (metadata order):
//   0: atomic_numbers int32[8192] (unused)  1: positions f32[8192*3]
//   2: r2r4 f32[95] (unused)  3: a1  4: a2  5: s6  6: s8
// Output: f32[1]

#define N_ATOMS  8192
#define TPB      128
#define TILE     512                    // atoms per symmetric tile
#define NTILES   (N_ATOMS / TILE)       // 16
#define NPAIRS   (NTILES * (NTILES + 1) / 2) // 136
#define JSPLIT   8                      // j-chunks per tile pair
#define JCHUNK   (TILE / JSPLIT)        // 64
#define NBLOCKS  (NPAIRS * JSPLIT)      // 1088

typedef unsigned long long u64;

__device__ float        g_partials[NBLOCKS];
__device__ unsigned int g_count = 0;

__device__ __forceinline__ u64 pack2(float lo, float hi) {
    u64 d; asm("mov.b64 %0, {%1, %2};" : "=l"(d) : "f"(lo), "f"(hi)); return d;
}
__device__ __forceinline__ void unpack2(float& lo, float& hi, u64 v) {
    asm("mov.b64 {%0, %1}, %2;" : "=f"(lo), "=f"(hi) : "l"(v));
}
__device__ __forceinline__ u64 ffma2(u64 a, u64 b, u64 c) {
    u64 d; asm("fma.rn.f32x2 %0, %1, %2, %3;" : "=l"(d) : "l"(a), "l"(b), "l"(c)); return d;
}
__device__ __forceinline__ u64 fmul2(u64 a, u64 b) {
    u64 d; asm("mul.rn.f32x2 %0, %1, %2;" : "=l"(d) : "l"(a), "l"(b)); return d;
}
__device__ __forceinline__ u64 fadd2(u64 a, u64 b) {
    u64 d; asm("add.rn.f32x2 %0, %1, %2;" : "=l"(d) : "l"(a), "l"(b)); return d;
}
__device__ __forceinline__ float frcp(float x) {
    float r; asm("rcp.approx.ftz.f32 %0, %1;" : "=f"(r) : "f"(x)); return r;
}

__global__ __launch_bounds__(TPB) void d3_pair_tri2(
    const float* __restrict__ pos,
    const float* __restrict__ a1p, const float* __restrict__ a2p,
    const float* __restrict__ s6p, const float* __restrict__ s8p,
    float* __restrict__ out)
{
    // j-chunk in shared, lane-duplicated for f32x2 broadcast:
    //   sjA[j] = { (-2xj,-2xj), (-2yj,-2yj) },  sjB[j] = { (-2zj,-2zj), (nj,nj) }
    __shared__ ulonglong2 sjA[JCHUNK];
    __shared__ ulonglong2 sjB[JCHUNK];
    __shared__ float s_wsum[TPB / 32];
    __shared__ int   s_last;

    const float a1 = *a1p, a2 = *a2p;
    const float s6 = *s6p, s8 = *s8p;
    const float t  = a1 + a2;
    const float t2 = t * t;
    const float t6 = t2 * t2 * t2;
    const float t8 = t6 * t2;
    const float C6 = t6 + 1e-12f;
    const float C8 = t8 + 1e-12f;

    const u64 C6p = pack2(C6, C6);
    const u64 C8p = pack2(C8, C8);
    const u64 s6n = pack2(-s6, -s6);
    const u64 s8n = pack2(-s8, -s8);

    // Decode block -> (tile_i, tile_j, j-chunk), upper triangle ti <= tj.
    int p  = blockIdx.x >> 3;        // unordered tile-pair index [0,136)
    const int jh = blockIdx.x & 7;   // j-chunk within the tile pair
    int ti = 0;
    while (p >= NTILES - ti) { p -= NTILES - ti; ++ti; }
    const int tj = ti + p;
    const float w = (ti == tj) ? 1.0f : 2.0f;

    // Load j-chunk into shared (first JCHUNK threads).
    const int j0 = tj * TILE + jh * JCHUNK;
    if (threadIdx.x < JCHUNK) {
        const int j = j0 + threadIdx.x;
        const float xj = pos[3 * j + 0];
        const float yj = pos[3 * j + 1];
        const float zj = pos[3 * j + 2];
        const float nj = fmaf(xj, xj, fmaf(yj, yj, zj * zj));
        sjA[threadIdx.x] = make_ulonglong2(pack2(-2.f * xj, -2.f * xj),
                                           pack2(-2.f * yj, -2.f * yj));
        sjB[threadIdx.x] = make_ulonglong2(pack2(-2.f * zj, -2.f * zj),
                                           pack2(nj, nj));
    }
    __syncthreads();

    // Four i-atoms per thread -> two independent packed streams.
    const int ibase = ti * TILE + threadIdx.x;
    float xi[4], yi[4], zi[4], ni[4];
#pragma unroll
    for (int k = 0; k < 4; ++k) {
        const int i = ibase + k * TPB;
        xi[k] = pos[3 * i + 0];
        yi[k] = pos[3 * i + 1];
        zi[k] = pos[3 * i + 2];
        ni[k] = fmaf(xi[k], xi[k], fmaf(yi[k], yi[k], zi[k] * zi[k]));
    }
    const u64 xA = pack2(xi[0], xi[1]), yA = pack2(yi[0], yi[1]);
    const u64 zA = pack2(zi[0], zi[1]), nA = pack2(ni[0], ni[1]);
    const u64 xB = pack2(xi[2], xi[3]), yB = pack2(yi[2], yi[3]);
    const u64 zB = pack2(zi[2], zi[3]), nB = pack2(ni[2], ni[3]);

    u64 accA = pack2(0.f, 0.f);
    u64 accB = pack2(0.f, 0.f);

#pragma unroll 4
    for (int j = 0; j < JCHUNK; ++j) {
        const ulonglong2 ja = sjA[j];
        const ulonglong2 jb = sjB[j];
        const u64 m2x = ja.x, m2y = ja.y, m2z = jb.x, njp = jb.y;

#define STREAM(X, Y, Z, NI, ACC)                                            \
        {                                                                   \
            u64 h  = fadd2(NI, njp);                /* ni + nj          */  \
            h      = ffma2(m2z, Z, h);                                      \
            h      = ffma2(m2y, Y, h);                                      \
            u64 d2 = ffma2(m2x, X, h);              /* |ri-rj|^2        */  \
            u64 d4 = fmul2(d2, d2);                                         \
            u64 A_ = ffma2(d4, d2, C6p);            /* d^6 + T6         */  \
            u64 B_ = ffma2(d4, d4, C8p);            /* d^8 + T8         */  \
            u64 P  = fmul2(A_, B_);                                         \
            u64 nm = ffma2(s8n, A_, fmul2(s6n, B_));/* -(s6 B + s8 A)   */  \
            float pl, ph; unpack2(pl, ph, P);                               \
            const u64 r = pack2(frcp(pl), frcp(ph));                        \
            ACC = ffma2(nm, r, ACC);                                        \
        }
        STREAM(xA, yA, zA, nA, accA)
        STREAM(xB, yB, zB, nB, accB)
#undef STREAM
    }

    float a0, a1h, b0, b1h;
    unpack2(a0, a1h, accA);
    unpack2(b0, b1h, accB);
    float v = ((a0 + a1h) + (b0 + b1h)) * w;    // tile-pair weight (1 or 2)

#pragma unroll
    for (int off = 16; off > 0; off >>= 1)
        v += __shfl_down_sync(0xFFFFFFFFu, v, off);
    if ((threadIdx.x & 31) == 0) s_wsum[threadIdx.x >> 5] = v;
    __syncthreads();

    if (threadIdx.x == 0) {
        float ws = 0.f;
#pragma unroll
        for (int k = 0; k < TPB / 32; ++k) ws += s_wsum[k];
        g_partials[blockIdx.x] = ws;
        __threadfence();
        const unsigned int old = atomicAdd(&g_count, 1u);
        s_last = (old == NBLOCKS - 1);
    }
    __syncthreads();

    // Last block: reduce all partials (fixed order -> deterministic),
    // add analytic self-pair correction, reset counter for graph replay.
    if (s_last) {
        __threadfence();
        const int tx = threadIdx.x;
        float v2 = 0.f;
        for (int idx = tx; idx < NBLOCKS; idx += TPB)
            v2 += g_partials[idx];
#pragma unroll
        for (int off = 16; off > 0; off >>= 1)
            v2 += __shfl_down_sync(0xFFFFFFFFu, v2, off);
        if ((tx & 31) == 0) s_wsum[tx >> 5] = v2;
        __syncthreads();
        if (tx == 0) {
            float tot = 0.f;
#pragma unroll
            for (int k = 0; k < TPB / 32; ++k) tot += s_wsum[k];
            const float diag = (float)N_ATOMS * (s6 / C6 + s8 / C8);
            out[0] = tot + diag;
            g_count = 0;
        }
    }
}

extern "C" void kernel_launch(void* const* d_in, const int* in_sizes, int n_in,
                              void* d_out, int out_size)
{
    (void)in_sizes; (void)n_in; (void)out_size;
    const float* pos = (const float*)d_in[1];
    const float* a1p = (const float*)d_in[3];
    const float* a2p = (const float*)d_in[4];
    const float* s6p = (const float*)d_in[5];
    const float* s8p = (const float*)d_in[6];
    float* out = (float*)d_out;

    d3_pair_tri2<<<NBLOCKS, TPB>>>(pos, a1p, a2p, s6p, s8p, out);
}

// round 10
// speedup vs baseline: 1.1001x; 1.1001x over previous
#include <cuda_runtime.h>

// KeopsDFTD3Module: all-pairs D3-BJ dispersion energy, N=8192, scalar output.
//   D_ij = -s6/(d2^3 + T6) - s8/(d2^4 + T8),  T6=(a1+a2)^6+eps, T8=(a1+a2)^8+eps
//   diagonal masked out. Output = sum_ij D_ij.
//
// R7: exact-symmetry triangle (d2 = ni+nj-2ri.rj is bitwise symmetric) with
// TWO packed f32x2 i-streams per thread for ILP (the R6 single-stream version
// was dependency-chain bound: fma% fell 57->39). 16 tiles of 512 atoms,
// 136 unordered tile pairs x 8 j-chunks = 1088 identical CTAs. Off-diagonal
// pairs weighted 2; self-pairs removed analytically. Fused last-block reduce.
//
// Inputs (metadata order):
//   0: atomic_numbers int32[8192] (unused)  1: positions f32[8192*3]
//   2: r2r4 f32[95] (unused)  3: a1  4: a2  5: s6  6: s8
// Output: f32[1]

#define N_ATOMS  8192
#define TPB      128
#define TILE     512                    // atoms per symmetric tile
#define NTILES   (N_ATOMS / TILE)       // 16
#define NPAIRS   (NTILES * (NTILES + 1) / 2) // 136
#define JSPLIT   8                      // j-chunks per tile pair
#define JCHUNK   (TILE / JSPLIT)        // 64
#define NBLOCKS  (NPAIRS * JSPLIT)      // 1088

typedef unsigned long long u64;

__device__ float        g_partials[NBLOCKS];
__device__ unsigned int g_count = 0;

__device__ __forceinline__ u64 pack2(float lo, float hi) {
    u64 d; asm("mov.b64 %0, {%1, %2};" : "=l"(d) : "f"(lo), "f"(hi)); return d;
}
__device__ __forceinline__ void unpack2(float& lo, float& hi, u64 v) {
    asm("mov.b64 {%0, %1}, %2;" : "=f"(lo), "=f"(hi) : "l"(v));
}
__device__ __forceinline__ u64 ffma2(u64 a, u64 b, u64 c) {
    u64 d; asm("fma.rn.f32x2 %0, %1, %2, %3;" : "=l"(d) : "l"(a), "l"(b), "l"(c)); return d;
}
__device__ __forceinline__ u64 fmul2(u64 a, u64 b) {
    u64 d; asm("mul.rn.f32x2 %0, %1, %2;" : "=l"(d) : "l"(a), "l"(b)); return d;
}
__device__ __forceinline__ u64 fadd2(u64 a, u64 b) {
    u64 d; asm("add.rn.f32x2 %0, %1, %2;" : "=l"(d) : "l"(a), "l"(b)); return d;
}
__device__ __forceinline__ float frcp(float x) {
    float r; asm("rcp.approx.ftz.f32 %0, %1;" : "=f"(r) : "f"(x)); return r;
}

__global__ __launch_bounds__(TPB) void d3_pair_tri2(
    const float* __restrict__ pos,
    const float* __restrict__ a1p, const float* __restrict__ a2p,
    const float* __restrict__ s6p, const float* __restrict__ s8p,
    float* __restrict__ out)
{
    // j-chunk in shared, lane-duplicated for f32x2 broadcast:
    //   sjA[j] = { (-2xj,-2xj), (-2yj,-2yj) },  sjB[j] = { (-2zj,-2zj), (nj,nj) }
    __shared__ ulonglong2 sjA[JCHUNK];
    __shared__ ulonglong2 sjB[JCHUNK];
    __shared__ float s_wsum[TPB / 32];
    __shared__ int   s_last;

    const float a1 = *a1p, a2 = *a2p;
    const float s6 = *s6p, s8 = *s8p;
    const float t  = a1 + a2;
    const float t2 = t * t;
    const float t6 = t2 * t2 * t2;
    const float t8 = t6 * t2;
    const float C6 = t6 + 1e-12f;
    const float C8 = t8 + 1e-12f;

    const u64 C6p = pack2(C6, C6);
    const u64 C8p = pack2(C8, C8);
    const u64 s6n = pack2(-s6, -s6);
    const u64 s8n = pack2(-s8, -s8);

    // Decode block -> (tile_i, tile_j, j-chunk), upper triangle ti <= tj.
    int p  = blockIdx.x >> 3;        // unordered tile-pair index [0,136)
    const int jh = blockIdx.x & 7;   // j-chunk within the tile pair
    int ti = 0;
    while (p >= NTILES - ti) { p -= NTILES - ti; ++ti; }
    const int tj = ti + p;
    const float w = (ti == tj) ? 1.0f : 2.0f;

    // Load j-chunk into shared (first JCHUNK threads).
    const int j0 = tj * TILE + jh * JCHUNK;
    if (threadIdx.x < JCHUNK) {
        const int j = j0 + threadIdx.x;
        const float xj = pos[3 * j + 0];
        const float yj = pos[3 * j + 1];
        const float zj = pos[3 * j + 2];
        const float nj = fmaf(xj, xj, fmaf(yj, yj, zj * zj));
        sjA[threadIdx.x] = make_ulonglong2(pack2(-2.f * xj, -2.f * xj),
                                           pack2(-2.f * yj, -2.f * yj));
        sjB[threadIdx.x] = make_ulonglong2(pack2(-2.f * zj, -2.f * zj),
                                           pack2(nj, nj));
    }
    __syncthreads();

    // Four i-atoms per thread -> two independent packed streams.
    const int ibase = ti * TILE + threadIdx.x;
    float xi[4], yi[4], zi[4], ni[4];
#pragma unroll
    for (int k = 0; k < 4; ++k) {
        const int i = ibase + k * TPB;
        xi[k] = pos[3 * i + 0];
        yi[k] = pos[3 * i + 1];
        zi[k] = pos[3 * i + 2];
        ni[k] = fmaf(xi[k], xi[k], fmaf(yi[k], yi[k], zi[k] * zi[k]));
    }
    const u64 xA = pack2(xi[0], xi[1]), yA = pack2(yi[0], yi[1]);
    const u64 zA = pack2(zi[0], zi[1]), nA = pack2(ni[0], ni[1]);
    const u64 xB = pack2(xi[2], xi[3]), yB = pack2(yi[2], yi[3]);
    const u64 zB = pack2(zi[2], zi[3]), nB = pack2(ni[2], ni[3]);

    u64 accA = pack2(0.f, 0.f);
    u64 accB = pack2(0.f, 0.f);

#pragma unroll 4
    for (int j = 0; j < JCHUNK; ++j) {
        const ulonglong2 ja = sjA[j];
        const ulonglong2 jb = sjB[j];
        const u64 m2x = ja.x, m2y = ja.y, m2z = jb.x, njp = jb.y;

#define STREAM(X, Y, Z, NI, ACC)                                            \
        {                                                                   \
            u64 h  = fadd2(NI, njp);                /* ni + nj          */  \
            h      = ffma2(m2z, Z, h);                                      \
            h      = ffma2(m2y, Y, h);                                      \
            u64 d2 = ffma2(m2x, X, h);              /* |ri-rj|^2        */  \
            u64 d4 = fmul2(d2, d2);                                         \
            u64 A_ = ffma2(d4, d2, C6p);            /* d^6 + T6         */  \
            u64 B_ = ffma2(d4, d4, C8p);            /* d^8 + T8         */  \
            u64 P  = fmul2(A_, B_);                                         \
            u64 nm = ffma2(s8n, A_, fmul2(s6n, B_));/* -(s6 B + s8 A)   */  \
            float pl, ph; unpack2(pl, ph, P);                               \
            const u64 r = pack2(frcp(pl), frcp(ph));                        \
            ACC = ffma2(nm, r, ACC);                                        \
        }
        STREAM(xA, yA, zA, nA, accA)
        STREAM(xB, yB, zB, nB, accB)
#undef STREAM
    }

    float a0, a1h, b0, b1h;
    unpack2(a0, a1h, accA);
    unpack2(b0, b1h, accB);
    float v = ((a0 + a1h) + (b0 + b1h)) * w;    // tile-pair weight (1 or 2)

#pragma unroll
    for (int off = 16; off > 0; off >>= 1)
        v += __shfl_down_sync(0xFFFFFFFFu, v, off);
    if ((threadIdx.x & 31) == 0) s_wsum[threadIdx.x >> 5] = v;
    __syncthreads();

    if (threadIdx.x == 0) {
        float ws = 0.f;
#pragma unroll
        for (int k = 0; k < TPB / 32; ++k) ws += s_wsum[k];
        g_partials[blockIdx.x] = ws;
        __threadfence();
        const unsigned int old = atomicAdd(&g_count, 1u);
        s_last = (old == NBLOCKS - 1);
    }
    __syncthreads();

    // Last block: reduce all partials (fixed order -> deterministic),
    // add analytic self-pair correction, reset counter for graph replay.
    if (s_last) {
        __threadfence();
        const int tx = threadIdx.x;
        float v2 = 0.f;
        for (int idx = tx; idx < NBLOCKS; idx += TPB)
            v2 += g_partials[idx];
#pragma unroll
        for (int off = 16; off > 0; off >>= 1)
            v2 += __shfl_down_sync(0xFFFFFFFFu, v2, off);
        if ((tx & 31) == 0) s_wsum[tx >> 5] = v2;
        __syncthreads();
        if (tx == 0) {
            float tot = 0.f;
#pragma unroll
            for (int k = 0; k < TPB / 32; ++k) tot += s_wsum[k];
            const float diag = (float)N_ATOMS * (s6 / C6 + s8 / C8);
            out[0] = tot + diag;
            g_count = 0;
        }
    }
}

extern "C" void kernel_launch(void* const* d_in, const int* in_sizes, int n_in,
                              void* d_out, int out_size)
{
    (void)in_sizes; (void)n_in; (void)out_size;
    const float* pos = (const float*)d_in[1];
    const float* a1p = (const float*)d_in[3];
    const float* a2p = (const float*)d_in[4];
    const float* s6p = (const float*)d_in[5];
    const float* s8p = (const float*)d_in[6];
    float* out = (float*)d_out;

    d3_pair_tri2<<<NBLOCKS, TPB>>>(pos, a1p, a2p, s6p, s8p, out);
}